// round 2
// baseline (speedup 1.0000x reference)
#include <cuda_runtime.h>
#include <math.h>

#define NF 32      // B*T frames
#define HW 2304    // 48*48 tokens per frame
#define CC 512
#define C3 1536
#define NH 8
#define DH 64
#define EPSV 1e-6f

// ---- scratch (no allocations allowed; __device__ globals) ----
static __device__ float g_xpart[NF*18*CC];     // partial channel sums over token slices
static __device__ float g_mmpart[NF*18];       // partial motion sums
static __device__ float g_mwt[NF];             // 1+tanh(mean motion) per frame
static __device__ float g_qkvt[NF*C3];         // temporal qkv
static __device__ float g_tout[NF*CC];         // temporal attention output
static __device__ float g_bias[NF*C3];         // (temporal_emb + t_out[f]) @ W
static __device__ float g_qkv[113246208];      // 32*2304*1536 spatial qkv (453MB)
static __device__ float g_kvpart[4*256*4096];  // per-slice kv partials
static __device__ float g_kspart[4*256*64];    // per-slice ksum partials
static __device__ float g_kv[256*4096];        // kv per (frame,head)
static __device__ float g_ksum[256*64];        // ksum per (frame,head)

__device__ __forceinline__ float fmap(float x){ return x > 0.f ? x + 1.f : __expf(x); }

// ---- K1: per-frame partial sums (channel means + motion mean), deterministic ----
__global__ void k_mean(const float* __restrict__ x, const float* __restrict__ mm){
    int f = blockIdx.x, s = blockIdx.y, tid = threadIdx.x;  // 512 threads
    const float* xp = x + ((size_t)f*HW + (size_t)s*128)*CC;
    float acc = 0.f;
    #pragma unroll 4
    for (int n = 0; n < 128; n++) acc += xp[(size_t)n*CC + tid];
    g_xpart[(f*18+s)*CC + tid] = acc;
    __shared__ float red[128];
    if (tid < 128) red[tid] = mm[f*HW + s*128 + tid];
    __syncthreads();
    for (int st = 64; st > 0; st >>= 1){
        if (tid < st) red[tid] += red[tid+st];
        __syncthreads();
    }
    if (tid == 0) g_mmpart[f*18+s] = red[0];
}

// ---- K2: finalize motion weights ----
__global__ void k_mw(){
    int f = threadIdx.x; // 32
    float s = 0.f;
    for (int i = 0; i < 18; i++) s += g_mmpart[f*18+i];
    g_mwt[f] = 1.f + tanhf(s * (1.f/HW));
}

// ---- K3: temporal qkv = x_time @ W ----
__global__ void k_tqkv(const float* __restrict__ W, const float* __restrict__ temb){
    int f = blockIdx.x; int cb = blockIdx.y*256; int tid = threadIdx.x; // 256 thr
    __shared__ float row[CC];
    for (int i = tid; i < CC; i += 256){
        float a = 0.f;
        for (int s = 0; s < 18; s++) a += g_xpart[(f*18+s)*CC + i];
        row[i] = a*(1.f/HW) + temb[i];
    }
    __syncthreads();
    int col = cb + tid;
    float acc = 0.f;
    #pragma unroll 8
    for (int k = 0; k < CC; k++) acc += row[k]*W[(size_t)k*C3 + col];
    g_qkvt[f*C3 + col] = acc;
}

// ---- K4: temporal linear attention (T=16, exact via 16x16 scores) ----
__global__ void k_tattn(){
    int b = blockIdx.x, h = blockIdx.y, tid = threadIdx.x; // 64 threads
    __shared__ float sq[16][64], sk[16][64], sv[16][64], sA[16][16];
    for (int t = 0; t < 16; t++){
        int base = (b*16+t)*C3 + h*DH + tid;
        sq[t][tid] = fmap(g_qkvt[base]) * g_mwt[b*16+t];
        sk[t][tid] = fmap(g_qkvt[base+512]);
        sv[t][tid] = g_qkvt[base+1024];
    }
    __syncthreads();
    for (int i = tid; i < 256; i += 64){
        int t = i >> 4, s2 = i & 15;
        float a = 0.f;
        #pragma unroll
        for (int d = 0; d < 64; d++) a += sq[t][d]*sk[s2][d];
        sA[t][s2] = a;
    }
    __syncthreads();
    for (int t = 0; t < 16; t++){
        float rs = 0.f, acc = 0.f;
        #pragma unroll
        for (int s2 = 0; s2 < 16; s2++){ rs += sA[t][s2]; acc += sA[t][s2]*sv[s2][tid]; }
        g_tout[(b*16+t)*CC + h*DH + tid] = acc / (rs + EPSV);
    }
}

// ---- K5: per-frame bias = (temporal_emb + t_out[f]) @ W ----
__global__ void k_bias(const float* __restrict__ W, const float* __restrict__ temb){
    int f = blockIdx.x; int cb = blockIdx.y*256; int tid = threadIdx.x;
    __shared__ float row[CC];
    for (int i = tid; i < CC; i += 256) row[i] = temb[i] + g_tout[f*CC+i];
    __syncthreads();
    int col = cb + tid;
    float acc = 0.f;
    #pragma unroll 8
    for (int k = 0; k < CC; k++) acc += row[k]*W[(size_t)k*C3 + col];
    g_bias[f*C3 + col] = acc;
}

// ---- K6: big GEMM  qkv[f] = x[f] @ W + bias[f]   (128x128x16 tiles, 8x8/thread) ----
__global__ void __launch_bounds__(256) k_gemm(const float* __restrict__ x, const float* __restrict__ W){
    int f = blockIdx.z;
    int mb = blockIdx.y * 128;
    int nb = blockIdx.x * 128;
    const float* A = x + (size_t)f*HW*CC;
    float* Cp = g_qkv + (size_t)f*HW*C3;
    __shared__ float As[16][128];
    __shared__ float Bs[16][128];
    int tid = threadIdx.x;
    int tx = tid & 15, ty = tid >> 4;
    int mreg = ty*8, nreg = tx*8;
    float acc[8][8] = {};
    for (int k0 = 0; k0 < CC; k0 += 16){
        #pragma unroll
        for (int i = 0; i < 2; i++){
            int l = tid*2 + i;
            int ar = l >> 2, ac = (l & 3) * 4;
            float4 va = *(const float4*)(A + (size_t)(mb+ar)*CC + k0 + ac);
            As[ac+0][ar] = va.x; As[ac+1][ar] = va.y; As[ac+2][ar] = va.z; As[ac+3][ar] = va.w;
            int br = l >> 5, bc = (l & 31)*4;
            *(float4*)&Bs[br][bc] = *(const float4*)(W + (size_t)(k0+br)*C3 + nb + bc);
        }
        __syncthreads();
        #pragma unroll
        for (int k = 0; k < 16; k++){
            float a[8], b[8];
            *(float4*)&a[0] = *(const float4*)&As[k][mreg];
            *(float4*)&a[4] = *(const float4*)&As[k][mreg+4];
            *(float4*)&b[0] = *(const float4*)&Bs[k][nreg];
            *(float4*)&b[4] = *(const float4*)&Bs[k][nreg+4];
            #pragma unroll
            for (int i = 0; i < 8; i++)
                #pragma unroll
                for (int j = 0; j < 8; j++)
                    acc[i][j] += a[i]*b[j];
        }
        __syncthreads();
    }
    const float* bias = g_bias + f*C3 + nb + nreg;
    float bv[8];
    #pragma unroll
    for (int j = 0; j < 8; j++) bv[j] = bias[j];
    #pragma unroll
    for (int i = 0; i < 8; i++){
        float* dst = Cp + (size_t)(mb+mreg+i)*C3 + nb + nreg;
        *(float4*)dst     = make_float4(acc[i][0]+bv[0], acc[i][1]+bv[1], acc[i][2]+bv[2], acc[i][3]+bv[3]);
        *(float4*)(dst+4) = make_float4(acc[i][4]+bv[4], acc[i][5]+bv[5], acc[i][6]+bv[6], acc[i][7]+bv[7]);
    }
}

// ---- K7: kv[f,h] = sum_n f(k)[n] (x) v[n], ksum[f,h] — deterministic partials ----
__global__ void __launch_bounds__(256) k_kv(){
    int sl = blockIdx.x, h = blockIdx.y, f = blockIdx.z, tid = threadIdx.x;
    int fh = f*NH + h;
    const float* base = g_qkv + (size_t)f*HW*C3;
    __shared__ float sk[64][64], sv[64][64];
    __shared__ float ksr[4][64];
    int col = tid & 63;
    int r0 = tid >> 6;              // 0..3
    int td = (tid >> 4) * 4;        // 0..60
    int te = (tid & 15) * 4;        // 0..60
    float acc[4][4] = {};
    float kscol = 0.f;
    for (int c = 0; c < 9; c++){
        int n0 = sl*576 + c*64;
        __syncthreads();
        #pragma unroll
        for (int i = 0; i < 16; i++){
            int row = r0 + i*4;
            const float* p = base + (size_t)(n0+row)*C3 + h*DH + col;
            float kv_ = fmap(p[512]);
            sk[row][col] = kv_;
            kscol += kv_;
            sv[row][col] = p[1024];
        }
        __syncthreads();
        #pragma unroll
        for (int s = 0; s < 64; s++){
            float4 ka4 = *(const float4*)&sk[s][td];
            float4 vb4 = *(const float4*)&sv[s][te];
            float ka[4] = {ka4.x,ka4.y,ka4.z,ka4.w};
            float vb[4] = {vb4.x,vb4.y,vb4.z,vb4.w};
            #pragma unroll
            for (int i = 0; i < 4; i++)
                #pragma unroll
                for (int j = 0; j < 4; j++)
                    acc[i][j] += ka[i]*vb[j];
        }
    }
    float* dst = g_kvpart + ((size_t)sl*256 + fh)*4096;
    #pragma unroll
    for (int i = 0; i < 4; i++){
        *(float4*)&dst[(td+i)*64 + te] = make_float4(acc[i][0],acc[i][1],acc[i][2],acc[i][3]);
    }
    __syncthreads();
    ksr[r0][col] = kscol;
    __syncthreads();
    if (tid < 64)
        g_kspart[((size_t)sl*256+fh)*64 + tid] = ksr[0][tid]+ksr[1][tid]+ksr[2][tid]+ksr[3][tid];
}

// ---- K8: reduce kv/ksum slice partials (fixed order) ----
__global__ void k_kvred(){
    int fh = blockIdx.x, tid = threadIdx.x; // 256 blocks x 256 threads
    #pragma unroll
    for (int i = 0; i < 16; i++){
        int idx = tid + i*256;
        float s = 0.f;
        #pragma unroll
        for (int sl = 0; sl < 4; sl++) s += g_kvpart[((size_t)sl*256+fh)*4096 + idx];
        g_kv[(size_t)fh*4096 + idx] = s;
    }
    if (tid < 64){
        float s = 0.f;
        #pragma unroll
        for (int sl = 0; sl < 4; sl++) s += g_kspart[((size_t)sl*256+fh)*64 + tid];
        g_ksum[fh*64+tid] = s;
    }
}

// ---- K9: out = mw * (f(q) @ kv) / (mw * (f(q)·ksum) + eps) ----
__global__ void __launch_bounds__(256) k_out(const float* __restrict__ mm, float* __restrict__ out){
    int tb = blockIdx.x, h = blockIdx.y, f = blockIdx.z, tid = threadIdx.x;
    int fh = f*NH + h;
    int n0 = tb*64;
    __shared__ float sq[64][64];
    __shared__ float skv[64][64];
    __shared__ float sks[64], smw[64];
    if (tid < 64){
        sks[tid] = g_ksum[fh*64+tid];
        smw[tid] = 1.f + tanhf(mm[f*HW + n0 + tid]);
    }
    {
        float* kvf = &skv[0][0];
        const float* src = g_kv + (size_t)fh*4096;
        #pragma unroll
        for (int i = 0; i < 16; i++) kvf[tid + i*256] = src[tid + i*256];
    }
    int col = tid & 63, r0 = tid >> 6;
    const float* qb = g_qkv + (size_t)f*HW*C3 + h*DH + col;
    #pragma unroll
    for (int i = 0; i < 16; i++){
        int row = r0 + i*4;
        sq[row][col] = fmap(qb[(size_t)(n0+row)*C3]);
    }
    __syncthreads();
    int tn = (tid >> 4)*4, te = (tid & 15)*4;
    float acc[4][4] = {};
    float z[4] = {};
    #pragma unroll 8
    for (int d = 0; d < 64; d++){
        float ks = sks[d];
        float4 vb4 = *(const float4*)&skv[d][te];
        float vb[4] = {vb4.x,vb4.y,vb4.z,vb4.w};
        #pragma unroll
        for (int i = 0; i < 4; i++){
            float q = sq[tn+i][d];
            z[i] += q*ks;
            #pragma unroll
            for (int j = 0; j < 4; j++) acc[i][j] += q*vb[j];
        }
    }
    #pragma unroll
    for (int i = 0; i < 4; i++){
        float w = smw[tn+i];
        float inv = w / (w*z[i] + EPSV);
        float4 o = make_float4(acc[i][0]*inv, acc[i][1]*inv, acc[i][2]*inv, acc[i][3]*inv);
        *(float4*)(out + (size_t)(f*HW + n0 + tn + i)*CC + h*DH + te) = o;
    }
}

extern "C" void kernel_launch(void* const* d_in, const int* in_sizes, int n_in,
                              void* d_out, int out_size){
    const float* x    = (const float*)d_in[0];
    const float* mm   = (const float*)d_in[1];
    const float* W    = (const float*)d_in[2];
    const float* temb = (const float*)d_in[3];
    float* out = (float*)d_out;

    k_mean <<<dim3(32,18), 512>>>(x, mm);
    k_mw   <<<1, 32>>>();
    k_tqkv <<<dim3(32,6), 256>>>(W, temb);
    k_tattn<<<dim3(2,8), 64>>>();
    k_bias <<<dim3(32,6), 256>>>(W, temb);
    k_gemm <<<dim3(12,18,32), 256>>>(x, W);
    k_kv   <<<dim3(4,8,32), 256>>>();
    k_kvred<<<256, 256>>>();
    k_out  <<<dim3(36,8,32), 256>>>(mm, out);
}

// round 7
// speedup vs baseline: 1.0447x; 1.0447x over previous
#include <cuda_runtime.h>
#include <cuda_bf16.h>
#include <math.h>
#include <stdint.h>

#define NF 32      // B*T frames
#define HW 2304    // 48*48 tokens per frame
#define CC 512
#define C3 1536
#define NH 8
#define DH 64
#define EPSV 1e-6f

// ---- scratch (__device__ globals; no allocations allowed) ----
static __device__ float g_xpart[NF*18*CC];
static __device__ float g_mmpart[NF*18];
static __device__ float g_mwt[NF];
static __device__ float g_qkvt[NF*C3];
static __device__ float g_tout[NF*CC];
static __device__ float g_bias[NF*C3];
static __device__ float g_qkv[113246208];                  // 32*2304*1536 f32
static __device__ __nv_bfloat16 g_xhi[NF*HW*CC];           // 75.5MB
static __device__ __nv_bfloat16 g_xlo[NF*HW*CC];
static __device__ __nv_bfloat16 g_wthi[C3*CC];             // W^T split, [1536][512]
static __device__ __nv_bfloat16 g_wtlo[C3*CC];
static __device__ float g_kvpart[4*256*4096];
static __device__ float g_kspart[4*256*64];
static __device__ float g_kv[256*4096];
static __device__ float g_ksum[256*64];

__device__ __forceinline__ float fmap(float x){ return x > 0.f ? x + 1.f : __expf(x); }

__device__ __forceinline__ uint32_t smem_to_u32(const void* p){
    uint32_t a;
    asm("{ .reg .u64 t; cvta.to.shared.u64 t, %1; cvt.u32.u64 %0, t; }" : "=r"(a) : "l"(p));
    return a;
}
__device__ __forceinline__ void cpa16(uint32_t saddr, const void* g){
    asm volatile("cp.async.cg.shared.global [%0], [%1], 16;" :: "r"(saddr), "l"(g));
}
__device__ __forceinline__ void ldsm4(uint32_t (&r)[4], uint32_t addr){
    asm volatile("ldmatrix.sync.aligned.m8n8.x4.shared.b16 {%0,%1,%2,%3}, [%4];"
        : "=r"(r[0]),"=r"(r[1]),"=r"(r[2]),"=r"(r[3]) : "r"(addr));
}
__device__ __forceinline__ void mma_bf16(float (&d)[4], const uint32_t (&a)[4], uint32_t b0, uint32_t b1){
    asm volatile("mma.sync.aligned.m16n8k16.row.col.f32.bf16.bf16.f32 "
        "{%0,%1,%2,%3},{%4,%5,%6,%7},{%8,%9},{%0,%1,%2,%3};"
        : "+f"(d[0]),"+f"(d[1]),"+f"(d[2]),"+f"(d[3])
        : "r"(a[0]),"r"(a[1]),"r"(a[2]),"r"(a[3]), "r"(b0),"r"(b1));
}

// ---- prep: split+transpose W into bf16 hi/lo [N=1536][K=512] ----
__global__ void k_prep_w(const float* __restrict__ W){
    __shared__ float t[32][33];
    int n0 = blockIdx.x*32, k0 = blockIdx.y*32;
    int tx = threadIdx.x, ty = threadIdx.y;
    #pragma unroll
    for (int i = 0; i < 32; i += 8)
        t[ty+i][tx] = W[(size_t)(k0+ty+i)*C3 + n0+tx];
    __syncthreads();
    #pragma unroll
    for (int i = 0; i < 32; i += 8){
        float v = t[tx][ty+i];
        __nv_bfloat16 hi = __float2bfloat16(v);
        __nv_bfloat16 lo = __float2bfloat16(v - __bfloat162float(hi));
        size_t idx = (size_t)(n0+ty+i)*CC + k0+tx;
        g_wthi[idx] = hi; g_wtlo[idx] = lo;
    }
}

// ---- prep: split x into bf16 hi/lo ----
__global__ void k_prep_x(const float* __restrict__ x){
    size_t i = ((size_t)blockIdx.x*256 + threadIdx.x)*4;
    float4 v = *(const float4*)(x + i);
    __nv_bfloat16 h0=__float2bfloat16(v.x), h1=__float2bfloat16(v.y),
                  h2=__float2bfloat16(v.z), h3=__float2bfloat16(v.w);
    __nv_bfloat162 hi01, hi23, lo01, lo23;
    hi01.x=h0; hi01.y=h1; hi23.x=h2; hi23.y=h3;
    lo01.x=__float2bfloat16(v.x-__bfloat162float(h0));
    lo01.y=__float2bfloat16(v.y-__bfloat162float(h1));
    lo23.x=__float2bfloat16(v.z-__bfloat162float(h2));
    lo23.y=__float2bfloat16(v.w-__bfloat162float(h3));
    *(__nv_bfloat162*)(g_xhi+i) = hi01; *(__nv_bfloat162*)(g_xhi+i+2) = hi23;
    *(__nv_bfloat162*)(g_xlo+i) = lo01; *(__nv_bfloat162*)(g_xlo+i+2) = lo23;
}

// ---- K1: per-frame partial sums ----
__global__ void k_mean(const float* __restrict__ x, const float* __restrict__ mm){
    int f = blockIdx.x, s = blockIdx.y, tid = threadIdx.x;
    const float* xp = x + ((size_t)f*HW + (size_t)s*128)*CC;
    float acc = 0.f;
    #pragma unroll 4
    for (int n = 0; n < 128; n++) acc += xp[(size_t)n*CC + tid];
    g_xpart[(f*18+s)*CC + tid] = acc;
    __shared__ float red[128];
    if (tid < 128) red[tid] = mm[f*HW + s*128 + tid];
    __syncthreads();
    for (int st = 64; st > 0; st >>= 1){
        if (tid < st) red[tid] += red[tid+st];
        __syncthreads();
    }
    if (tid == 0) g_mmpart[f*18+s] = red[0];
}

__global__ void k_mw(){
    int f = threadIdx.x;
    float s = 0.f;
    for (int i = 0; i < 18; i++) s += g_mmpart[f*18+i];
    g_mwt[f] = 1.f + tanhf(s * (1.f/HW));
}

__global__ void k_tqkv(const float* __restrict__ W, const float* __restrict__ temb){
    int f = blockIdx.x; int cb = blockIdx.y*256; int tid = threadIdx.x;
    __shared__ float row[CC];
    for (int i = tid; i < CC; i += 256){
        float a = 0.f;
        for (int s = 0; s < 18; s++) a += g_xpart[(f*18+s)*CC + i];
        row[i] = a*(1.f/HW) + temb[i];
    }
    __syncthreads();
    int col = cb + tid;
    float acc = 0.f;
    #pragma unroll 8
    for (int k = 0; k < CC; k++) acc += row[k]*W[(size_t)k*C3 + col];
    g_qkvt[f*C3 + col] = acc;
}

__global__ void k_tattn(){
    int b = blockIdx.x, h = blockIdx.y, tid = threadIdx.x;
    __shared__ float sq[16][64], sk[16][64], sv[16][64], sA[16][16];
    for (int t = 0; t < 16; t++){
        int base = (b*16+t)*C3 + h*DH + tid;
        sq[t][tid] = fmap(g_qkvt[base]) * g_mwt[b*16+t];
        sk[t][tid] = fmap(g_qkvt[base+512]);
        sv[t][tid] = g_qkvt[base+1024];
    }
    __syncthreads();
    for (int i = tid; i < 256; i += 64){
        int t = i >> 4, s2 = i & 15;
        float a = 0.f;
        #pragma unroll
        for (int d = 0; d < 64; d++) a += sq[t][d]*sk[s2][d];
        sA[t][s2] = a;
    }
    __syncthreads();
    for (int t = 0; t < 16; t++){
        float rs = 0.f, acc = 0.f;
        #pragma unroll
        for (int s2 = 0; s2 < 16; s2++){ rs += sA[t][s2]; acc += sA[t][s2]*sv[s2][tid]; }
        g_tout[(b*16+t)*CC + h*DH + tid] = acc / (rs + EPSV);
    }
}

__global__ void k_bias(const float* __restrict__ W, const float* __restrict__ temb){
    int f = blockIdx.x; int cb = blockIdx.y*256; int tid = threadIdx.x;
    __shared__ float row[CC];
    for (int i = tid; i < CC; i += 256) row[i] = temb[i] + g_tout[f*CC+i];
    __syncthreads();
    int col = cb + tid;
    float acc = 0.f;
    #pragma unroll 8
    for (int k = 0; k < CC; k++) acc += row[k]*W[(size_t)k*C3 + col];
    g_bias[f*C3 + col] = acc;
}

// ============ HMMA GEMM: qkv[f] = x[f] @ W + bias[f] (split-bf16) ============
// CTA tile M128xN128, warp tile 64x32, K chunks of 32, 3-stage cp.async pipeline.
// SMEM row pitch 80B -> ldmatrix conflict-free (20*r mod 32 is a permutation).
#define ROWP 80
#define MAT_SZ (128*ROWP)          // 10240 per matrix
#define STAGE_SZ (4*MAT_SZ)        // Ahi,Alo,Bhi,Blo = 40960
#define GEMM_SMEM (3*STAGE_SZ)     // 122880

__device__ __forceinline__ void load_stage(uint32_t sb,
        const __nv_bfloat16* __restrict__ aHi, const __nv_bfloat16* __restrict__ aLo,
        const __nv_bfloat16* __restrict__ bHi, const __nv_bfloat16* __restrict__ bLo,
        int k0, int tid){
    #pragma unroll
    for (int i = 0; i < 2; i++){
        int idx = tid + i*256;
        int row = idx >> 2, seg = idx & 3;
        uint32_t soff = (uint32_t)(row*ROWP + seg*16);
        size_t goff = (size_t)row*CC + k0 + seg*8;
        cpa16(sb + 0*MAT_SZ + soff, aHi + goff);
        cpa16(sb + 1*MAT_SZ + soff, aLo + goff);
        cpa16(sb + 2*MAT_SZ + soff, bHi + goff);
        cpa16(sb + 3*MAT_SZ + soff, bLo + goff);
    }
}

__global__ void __launch_bounds__(256) k_gemm_mma(){
    extern __shared__ char smem[];
    uint32_t sb0 = smem_to_u32(smem);
    int tid = threadIdx.x, wid = tid >> 5, lane = tid & 31;
    int nb = blockIdx.x * 128;
    int mb = blockIdx.y * 128;
    int f  = blockIdx.z;

    const __nv_bfloat16* aHi = g_xhi + ((size_t)f*HW + mb)*CC;
    const __nv_bfloat16* aLo = g_xlo + ((size_t)f*HW + mb)*CC;
    const __nv_bfloat16* bHi = g_wthi + (size_t)nb*CC;
    const __nv_bfloat16* bLo = g_wtlo + (size_t)nb*CC;

    load_stage(sb0 + 0*STAGE_SZ, aHi, aLo, bHi, bLo, 0, tid);
    asm volatile("cp.async.commit_group;" ::: "memory");
    load_stage(sb0 + 1*STAGE_SZ, aHi, aLo, bHi, bLo, 32, tid);
    asm volatile("cp.async.commit_group;" ::: "memory");

    float acc[4][4][4] = {};
    int wm = (wid >> 2) * 64, wn = (wid & 3) * 32;
    int lrow = lane & 15, lk = lane >> 4;

    #pragma unroll 1
    for (int ks = 0; ks < 16; ks++){
        asm volatile("cp.async.wait_group 1;" ::: "memory");
        __syncthreads();
        uint32_t st = sb0 + (uint32_t)((ks%3)*STAGE_SZ);
        #pragma unroll
        for (int s = 0; s < 2; s++){
            uint32_t ahf[4][4], alf[4][4];
            #pragma unroll
            for (int mi = 0; mi < 4; mi++){
                uint32_t addr = st + (uint32_t)((wm + mi*16 + lrow)*ROWP + s*32 + lk*16);
                ldsm4(ahf[mi], addr);
                ldsm4(alf[mi], addr + MAT_SZ);
            }
            uint32_t bhf[2][4], blf[2][4];
            #pragma unroll
            for (int nj = 0; nj < 2; nj++){
                uint32_t addr = st + 2*MAT_SZ + (uint32_t)((wn + nj*16 + lrow)*ROWP + s*32 + lk*16);
                ldsm4(bhf[nj], addr);
                ldsm4(blf[nj], addr + MAT_SZ);
            }
            #pragma unroll
            for (int mi = 0; mi < 4; mi++)
                #pragma unroll
                for (int ni = 0; ni < 4; ni++){
                    uint32_t bh0 = bhf[ni>>1][ni&1], bh1 = bhf[ni>>1][(ni&1)+2];
                    uint32_t bl0 = blf[ni>>1][ni&1], bl1 = blf[ni>>1][(ni&1)+2];
                    mma_bf16(acc[mi][ni], ahf[mi], bh0, bh1);
                    mma_bf16(acc[mi][ni], ahf[mi], bl0, bl1);
                    mma_bf16(acc[mi][ni], alf[mi], bh0, bh1);
                }
        }
        __syncthreads();
        if (ks + 2 < 16)
            load_stage(sb0 + (uint32_t)(((ks+2)%3)*STAGE_SZ), aHi, aLo, bHi, bLo, (ks+2)*32, tid);
        asm volatile("cp.async.commit_group;" ::: "memory");
    }

    // epilogue: registers -> global with bias
    const float* bias = g_bias + f*C3 + nb;
    float* base = g_qkv + ((size_t)f*HW + mb)*C3 + nb;
    int r0 = lane >> 2, cp0 = (lane & 3) * 2;
    #pragma unroll
    for (int mi = 0; mi < 4; mi++){
        #pragma unroll
        for (int ni = 0; ni < 4; ni++){
            int col = wn + ni*8 + cp0;
            float b0 = bias[col], b1 = bias[col+1];
            float* p0 = base + (size_t)(wm + mi*16 + r0)*C3 + col;
            p0[0] = acc[mi][ni][0] + b0;
            p0[1] = acc[mi][ni][1] + b1;
            float* p1 = p0 + (size_t)8*C3;
            p1[0] = acc[mi][ni][2] + b0;
            p1[1] = acc[mi][ni][3] + b1;
        }
    }
}

// ---- K7: kv partials ----
__global__ void __launch_bounds__(256) k_kv(){
    int sl = blockIdx.x, h = blockIdx.y, f = blockIdx.z, tid = threadIdx.x;
    int fh = f*NH + h;
    const float* base = g_qkv + (size_t)f*HW*C3;
    __shared__ float sk[64][64], sv[64][64];
    __shared__ float ksr[4][64];
    int col = tid & 63;
    int r0 = tid >> 6;
    int td = (tid >> 4) * 4;
    int te = (tid & 15) * 4;
    float acc[4][4] = {};
    float kscol = 0.f;
    for (int c = 0; c < 9; c++){
        int n0 = sl*576 + c*64;
        __syncthreads();
        #pragma unroll
        for (int i = 0; i < 16; i++){
            int row = r0 + i*4;
            const float* p = base + (size_t)(n0+row)*C3 + h*DH + col;
            float kv_ = fmap(p[512]);
            sk[row][col] = kv_;
            kscol += kv_;
            sv[row][col] = p[1024];
        }
        __syncthreads();
        #pragma unroll
        for (int s = 0; s < 64; s++){
            float4 ka4 = *(const float4*)&sk[s][td];
            float4 vb4 = *(const float4*)&sv[s][te];
            float ka[4] = {ka4.x,ka4.y,ka4.z,ka4.w};
            float vb[4] = {vb4.x,vb4.y,vb4.z,vb4.w};
            #pragma unroll
            for (int i = 0; i < 4; i++)
                #pragma unroll
                for (int j = 0; j < 4; j++)
                    acc[i][j] += ka[i]*vb[j];
        }
    }
    float* dst = g_kvpart + ((size_t)sl*256 + fh)*4096;
    #pragma unroll
    for (int i = 0; i < 4; i++)
        *(float4*)&dst[(td+i)*64 + te] = make_float4(acc[i][0],acc[i][1],acc[i][2],acc[i][3]);
    __syncthreads();
    ksr[r0][col] = kscol;
    __syncthreads();
    if (tid < 64)
        g_kspart[((size_t)sl*256+fh)*64 + tid] = ksr[0][tid]+ksr[1][tid]+ksr[2][tid]+ksr[3][tid];
}

__global__ void k_kvred(){
    int fh = blockIdx.x, tid = threadIdx.x;
    #pragma unroll
    for (int i = 0; i < 16; i++){
        int idx = tid + i*256;
        float s = 0.f;
        #pragma unroll
        for (int sl = 0; sl < 4; sl++) s += g_kvpart[((size_t)sl*256+fh)*4096 + idx];
        g_kv[(size_t)fh*4096 + idx] = s;
    }
    if (tid < 64){
        float s = 0.f;
        #pragma unroll
        for (int sl = 0; sl < 4; sl++) s += g_kspart[((size_t)sl*256+fh)*64 + tid];
        g_ksum[fh*64+tid] = s;
    }
}

__global__ void __launch_bounds__(256) k_out(const float* __restrict__ mm, float* __restrict__ out){
    int tb = blockIdx.x, h = blockIdx.y, f = blockIdx.z, tid = threadIdx.x;
    int fh = f*NH + h;
    int n0 = tb*64;
    __shared__ float sq[64][64];
    __shared__ float skv[64][64];
    __shared__ float sks[64], smw[64];
    if (tid < 64){
        sks[tid] = g_ksum[fh*64+tid];
        smw[tid] = 1.f + tanhf(mm[f*HW + n0 + tid]);
    }
    {
        float* kvf = &skv[0][0];
        const float* src = g_kv + (size_t)fh*4096;
        #pragma unroll
        for (int i = 0; i < 16; i++) kvf[tid + i*256] = src[tid + i*256];
    }
    int col = tid & 63, r0 = tid >> 6;
    const float* qb = g_qkv + (size_t)f*HW*C3 + h*DH + col;
    #pragma unroll
    for (int i = 0; i < 16; i++){
        int row = r0 + i*4;
        sq[row][col] = fmap(qb[(size_t)(n0+row)*C3]);
    }
    __syncthreads();
    int tn = (tid >> 4)*4, te = (tid & 15)*4;
    float acc[4][4] = {};
    float z[4] = {};
    #pragma unroll 8
    for (int d = 0; d < 64; d++){
        float ks = sks[d];
        float4 vb4 = *(const float4*)&skv[d][te];
        float vb[4] = {vb4.x,vb4.y,vb4.z,vb4.w};
        #pragma unroll
        for (int i = 0; i < 4; i++){
            float q = sq[tn+i][d];
            z[i] += q*ks;
            #pragma unroll
            for (int j = 0; j < 4; j++) acc[i][j] += q*vb[j];
        }
    }
    #pragma unroll
    for (int i = 0; i < 4; i++){
        float w = smw[tn+i];
        float inv = w / (w*z[i] + EPSV);
        float4 o = make_float4(acc[i][0]*inv, acc[i][1]*inv, acc[i][2]*inv, acc[i][3]*inv);
        *(float4*)(out + (size_t)(f*HW + n0 + tn + i)*CC + h*DH + te) = o;
    }
}

extern "C" void kernel_launch(void* const* d_in, const int* in_sizes, int n_in,
                              void* d_out, int out_size){
    const float* x    = (const float*)d_in[0];
    const float* mm   = (const float*)d_in[1];
    const float* W    = (const float*)d_in[2];
    const float* temb = (const float*)d_in[3];
    float* out = (float*)d_out;

    static int smem_set = 0;
    if (!smem_set){
        cudaFuncSetAttribute(k_gemm_mma, cudaFuncAttributeMaxDynamicSharedMemorySize, GEMM_SMEM);
        smem_set = 1;
    }

    k_prep_w<<<dim3(48,16), dim3(32,8)>>>(W);
    k_prep_x<<<36864, 256>>>(x);
    k_mean <<<dim3(32,18), 512>>>(x, mm);
    k_mw   <<<1, 32>>>();
    k_tqkv <<<dim3(32,6), 256>>>(W, temb);
    k_tattn<<<dim3(2,8), 64>>>();
    k_bias <<<dim3(32,6), 256>>>(W, temb);
    k_gemm_mma<<<dim3(12,18,32), 256, GEMM_SMEM>>>();
    k_kv   <<<dim3(4,8,32), 256>>>();
    k_kvred<<<256, 256>>>();
    k_out  <<<dim3(36,8,32), 256>>>(mm, out);
}

// round 10
// speedup vs baseline: 1.8297x; 1.7515x over previous
#include <cuda_runtime.h>
#include <cuda_bf16.h>
#include <math.h>
#include <stdint.h>

#define NF 32      // B*T frames
#define HW 2304    // 48*48 tokens per frame
#define CC 512
#define C3 1536
#define NH 8
#define DH 64
#define EPSV 1e-6f

// ---- scratch (__device__ globals; no allocations allowed) ----
static __device__ float g_xpart[NF*18*CC];
static __device__ float g_mmpart[NF*18];
static __device__ float g_mwt[NF];
static __device__ float g_qkvt[NF*C3];
static __device__ float g_tout[NF*CC];
static __device__ float g_bias[NF*C3];
static __device__ float g_qkv[113246208];                  // 32*2304*1536 f32
static __device__ __nv_bfloat16 g_xhi[NF*HW*CC];           // 75.5MB
static __device__ __nv_bfloat16 g_xlo[NF*HW*CC];
static __device__ __nv_bfloat16 g_wthi[C3*CC];             // W^T split, [1536][512]
static __device__ __nv_bfloat16 g_wtlo[C3*CC];
static __device__ float g_kvpart[4*256*4096];
static __device__ float g_kspart[4*256*64];
static __device__ float g_kv[256*4096];
static __device__ float g_ksum[256*64];

__device__ __forceinline__ float fmap(float x){ return x > 0.f ? x + 1.f : __expf(x); }

__device__ __forceinline__ uint32_t smem_to_u32(const void* p){
    uint32_t a;
    asm("{ .reg .u64 t; cvta.to.shared.u64 t, %1; cvt.u32.u64 %0, t; }" : "=r"(a) : "l"(p));
    return a;
}
__device__ __forceinline__ void cpa16(uint32_t saddr, const void* g){
    asm volatile("cp.async.cg.shared.global [%0], [%1], 16;" :: "r"(saddr), "l"(g));
}
__device__ __forceinline__ void ldsm4(uint32_t (&r)[4], uint32_t addr){
    asm volatile("ldmatrix.sync.aligned.m8n8.x4.shared.b16 {%0,%1,%2,%3}, [%4];"
        : "=r"(r[0]),"=r"(r[1]),"=r"(r[2]),"=r"(r[3]) : "r"(addr));
}
__device__ __forceinline__ void mma_bf16(float (&d)[4], const uint32_t (&a)[4], uint32_t b0, uint32_t b1){
    asm volatile("mma.sync.aligned.m16n8k16.row.col.f32.bf16.bf16.f32 "
        "{%0,%1,%2,%3},{%4,%5,%6,%7},{%8,%9},{%0,%1,%2,%3};"
        : "+f"(d[0]),"+f"(d[1]),"+f"(d[2]),"+f"(d[3])
        : "r"(a[0]),"r"(a[1]),"r"(a[2]),"r"(a[3]), "r"(b0),"r"(b1));
}

// ---- prep: split+transpose W into bf16 hi/lo [N=1536][K=512] ----
__global__ void k_prep_w(const float* __restrict__ W){
    __shared__ float t[32][33];
    int n0 = blockIdx.x*32, k0 = blockIdx.y*32;
    int tx = threadIdx.x, ty = threadIdx.y;
    #pragma unroll
    for (int i = 0; i < 32; i += 8)
        t[ty+i][tx] = W[(size_t)(k0+ty+i)*C3 + n0+tx];
    __syncthreads();
    #pragma unroll
    for (int i = 0; i < 32; i += 8){
        float v = t[tx][ty+i];
        __nv_bfloat16 hi = __float2bfloat16(v);
        __nv_bfloat16 lo = __float2bfloat16(v - __bfloat162float(hi));
        size_t idx = (size_t)(n0+ty+i)*CC + k0+tx;
        g_wthi[idx] = hi; g_wtlo[idx] = lo;
    }
}

// ---- prep: split x into bf16 hi/lo ----
__global__ void k_prep_x(const float* __restrict__ x){
    size_t i = ((size_t)blockIdx.x*256 + threadIdx.x)*4;
    float4 v = *(const float4*)(x + i);
    __nv_bfloat16 h0=__float2bfloat16(v.x), h1=__float2bfloat16(v.y),
                  h2=__float2bfloat16(v.z), h3=__float2bfloat16(v.w);
    __nv_bfloat162 hi01, hi23, lo01, lo23;
    hi01.x=h0; hi01.y=h1; hi23.x=h2; hi23.y=h3;
    lo01.x=__float2bfloat16(v.x-__bfloat162float(h0));
    lo01.y=__float2bfloat16(v.y-__bfloat162float(h1));
    lo23.x=__float2bfloat16(v.z-__bfloat162float(h2));
    lo23.y=__float2bfloat16(v.w-__bfloat162float(h3));
    *(__nv_bfloat162*)(g_xhi+i) = hi01; *(__nv_bfloat162*)(g_xhi+i+2) = hi23;
    *(__nv_bfloat162*)(g_xlo+i) = lo01; *(__nv_bfloat162*)(g_xlo+i+2) = lo23;
}

// ---- K1: per-frame partial sums ----
__global__ void k_mean(const float* __restrict__ x, const float* __restrict__ mm){
    int f = blockIdx.x, s = blockIdx.y, tid = threadIdx.x;
    const float* xp = x + ((size_t)f*HW + (size_t)s*128)*CC;
    float acc = 0.f;
    #pragma unroll 4
    for (int n = 0; n < 128; n++) acc += xp[(size_t)n*CC + tid];
    g_xpart[(f*18+s)*CC + tid] = acc;
    __shared__ float red[128];
    if (tid < 128) red[tid] = mm[f*HW + s*128 + tid];
    __syncthreads();
    for (int st = 64; st > 0; st >>= 1){
        if (tid < st) red[tid] += red[tid+st];
        __syncthreads();
    }
    if (tid == 0) g_mmpart[f*18+s] = red[0];
}

__global__ void k_mw(){
    int f = threadIdx.x;
    float s = 0.f;
    for (int i = 0; i < 18; i++) s += g_mmpart[f*18+i];
    g_mwt[f] = 1.f + tanhf(s * (1.f/HW));
}

__global__ void k_tqkv(const float* __restrict__ W, const float* __restrict__ temb){
    int f = blockIdx.x; int cb = blockIdx.y*256; int tid = threadIdx.x;
    __shared__ float row[CC];
    for (int i = tid; i < CC; i += 256){
        float a = 0.f;
        for (int s = 0; s < 18; s++) a += g_xpart[(f*18+s)*CC + i];
        row[i] = a*(1.f/HW) + temb[i];
    }
    __syncthreads();
    int col = cb + tid;
    float acc = 0.f;
    #pragma unroll 8
    for (int k = 0; k < CC; k++) acc += row[k]*W[(size_t)k*C3 + col];
    g_qkvt[f*C3 + col] = acc;
}

__global__ void k_tattn(){
    int b = blockIdx.x, h = blockIdx.y, tid = threadIdx.x;
    __shared__ float sq[16][64], sk[16][64], sv[16][64], sA[16][16];
    for (int t = 0; t < 16; t++){
        int base = (b*16+t)*C3 + h*DH + tid;
        sq[t][tid] = fmap(g_qkvt[base]) * g_mwt[b*16+t];
        sk[t][tid] = fmap(g_qkvt[base+512]);
        sv[t][tid] = g_qkvt[base+1024];
    }
    __syncthreads();
    for (int i = tid; i < 256; i += 64){
        int t = i >> 4, s2 = i & 15;
        float a = 0.f;
        #pragma unroll
        for (int d = 0; d < 64; d++) a += sq[t][d]*sk[s2][d];
        sA[t][s2] = a;
    }
    __syncthreads();
    for (int t = 0; t < 16; t++){
        float rs = 0.f, acc = 0.f;
        #pragma unroll
        for (int s2 = 0; s2 < 16; s2++){ rs += sA[t][s2]; acc += sA[t][s2]*sv[s2][tid]; }
        g_tout[(b*16+t)*CC + h*DH + tid] = acc / (rs + EPSV);
    }
}

__global__ void k_bias(const float* __restrict__ W, const float* __restrict__ temb){
    int f = blockIdx.x; int cb = blockIdx.y*256; int tid = threadIdx.x;
    __shared__ float row[CC];
    for (int i = tid; i < CC; i += 256) row[i] = temb[i] + g_tout[f*CC+i];
    __syncthreads();
    int col = cb + tid;
    float acc = 0.f;
    #pragma unroll 8
    for (int k = 0; k < CC; k++) acc += row[k]*W[(size_t)k*C3 + col];
    g_bias[f*C3 + col] = acc;
}

// ============ HMMA GEMM: qkv[f] = x[f] @ W + bias[f] (split-bf16) ============
// CTA tile M128xN128, warp tile 64x32, K chunks of 32, 2-stage cp.async pipeline
// (80KB smem -> 2 CTAs/SM, 4 warps/SMSP). __launch_bounds__(256,2) caps regs at 128.
// SMEM row pitch 80B -> ldmatrix conflict-free (20*r mod 32 is a permutation).
#define ROWP 80
#define MAT_SZ (128*ROWP)          // 10240 per matrix
#define STAGE_SZ (4*MAT_SZ)        // Ahi,Alo,Bhi,Blo = 40960
#define GEMM_SMEM (2*STAGE_SZ)     // 81920

__device__ __forceinline__ void load_stage(uint32_t sb,
        const __nv_bfloat16* __restrict__ aHi, const __nv_bfloat16* __restrict__ aLo,
        const __nv_bfloat16* __restrict__ bHi, const __nv_bfloat16* __restrict__ bLo,
        int k0, int tid){
    #pragma unroll
    for (int i = 0; i < 2; i++){
        int idx = tid + i*256;
        int row = idx >> 2, seg = idx & 3;
        uint32_t soff = (uint32_t)(row*ROWP + seg*16);
        size_t goff = (size_t)row*CC + k0 + seg*8;
        cpa16(sb + 0*MAT_SZ + soff, aHi + goff);
        cpa16(sb + 1*MAT_SZ + soff, aLo + goff);
        cpa16(sb + 2*MAT_SZ + soff, bHi + goff);
        cpa16(sb + 3*MAT_SZ + soff, bLo + goff);
    }
}

__global__ void __launch_bounds__(256, 2) k_gemm_mma(){
    extern __shared__ char smem[];
    uint32_t sb0 = smem_to_u32(smem);
    int tid = threadIdx.x, wid = tid >> 5, lane = tid & 31;
    int nb = blockIdx.x * 128;
    int mb = blockIdx.y * 128;
    int f  = blockIdx.z;

    const __nv_bfloat16* aHi = g_xhi + ((size_t)f*HW + mb)*CC;
    const __nv_bfloat16* aLo = g_xlo + ((size_t)f*HW + mb)*CC;
    const __nv_bfloat16* bHi = g_wthi + (size_t)nb*CC;
    const __nv_bfloat16* bLo = g_wtlo + (size_t)nb*CC;

    load_stage(sb0 + 0*STAGE_SZ, aHi, aLo, bHi, bLo, 0, tid);
    asm volatile("cp.async.commit_group;" ::: "memory");
    load_stage(sb0 + 1*STAGE_SZ, aHi, aLo, bHi, bLo, 32, tid);
    asm volatile("cp.async.commit_group;" ::: "memory");

    float acc[4][4][4] = {};
    int wm = (wid >> 2) * 64, wn = (wid & 3) * 32;
    int lrow = lane & 15, lk = lane >> 4;

    #pragma unroll 1
    for (int ks = 0; ks < 16; ks++){
        asm volatile("cp.async.wait_group 1;" ::: "memory");
        __syncthreads();
        uint32_t st = sb0 + (uint32_t)((ks & 1)*STAGE_SZ);
        #pragma unroll
        for (int s = 0; s < 2; s++){
            // B fragments resident (16 regs), A fragments loaded per-mi (8 regs live)
            uint32_t bhf[2][4], blf[2][4];
            #pragma unroll
            for (int nj = 0; nj < 2; nj++){
                uint32_t addr = st + 2*MAT_SZ + (uint32_t)((wn + nj*16 + lrow)*ROWP + s*32 + lk*16);
                ldsm4(bhf[nj], addr);
                ldsm4(blf[nj], addr + MAT_SZ);
            }
            #pragma unroll
            for (int mi = 0; mi < 4; mi++){
                uint32_t ahf[4], alf[4];
                uint32_t addr = st + (uint32_t)((wm + mi*16 + lrow)*ROWP + s*32 + lk*16);
                ldsm4(ahf, addr);
                ldsm4(alf, addr + MAT_SZ);
                #pragma unroll
                for (int ni = 0; ni < 4; ni++){
                    uint32_t bh0 = bhf[ni>>1][ni&1], bh1 = bhf[ni>>1][(ni&1)+2];
                    uint32_t bl0 = blf[ni>>1][ni&1], bl1 = blf[ni>>1][(ni&1)+2];
                    mma_bf16(acc[mi][ni], ahf, bh0, bh1);
                    mma_bf16(acc[mi][ni], ahf, bl0, bl1);
                    mma_bf16(acc[mi][ni], alf, bh0, bh1);
                }
            }
        }
        __syncthreads();
        if (ks + 2 < 16)
            load_stage(st, aHi, aLo, bHi, bLo, (ks+2)*32, tid);
        asm volatile("cp.async.commit_group;" ::: "memory");
    }

    // epilogue: registers -> global with bias
    const float* bias = g_bias + f*C3 + nb;
    float* base = g_qkv + ((size_t)f*HW + mb)*C3 + nb;
    int r0 = lane >> 2, cp0 = (lane & 3) * 2;
    #pragma unroll
    for (int mi = 0; mi < 4; mi++){
        #pragma unroll
        for (int ni = 0; ni < 4; ni++){
            int col = wn + ni*8 + cp0;
            float b0 = bias[col], b1 = bias[col+1];
            float* p0 = base + (size_t)(wm + mi*16 + r0)*C3 + col;
            p0[0] = acc[mi][ni][0] + b0;
            p0[1] = acc[mi][ni][1] + b1;
            float* p1 = p0 + (size_t)8*C3;
            p1[0] = acc[mi][ni][2] + b0;
            p1[1] = acc[mi][ni][3] + b1;
        }
    }
}

// ---- K7: kv partials ----
__global__ void __launch_bounds__(256) k_kv(){
    int sl = blockIdx.x, h = blockIdx.y, f = blockIdx.z, tid = threadIdx.x;
    int fh = f*NH + h;
    const float* base = g_qkv + (size_t)f*HW*C3;
    __shared__ float sk[64][64], sv[64][64];
    __shared__ float ksr[4][64];
    int col = tid & 63;
    int r0 = tid >> 6;
    int td = (tid >> 4) * 4;
    int te = (tid & 15) * 4;
    float acc[4][4] = {};
    float kscol = 0.f;
    for (int c = 0; c < 9; c++){
        int n0 = sl*576 + c*64;
        __syncthreads();
        #pragma unroll
        for (int i = 0; i < 16; i++){
            int row = r0 + i*4;
            const float* p = base + (size_t)(n0+row)*C3 + h*DH + col;
            float kv_ = fmap(p[512]);
            sk[row][col] = kv_;
            kscol += kv_;
            sv[row][col] = p[1024];
        }
        __syncthreads();
        #pragma unroll
        for (int s = 0; s < 64; s++){
            float4 ka4 = *(const float4*)&sk[s][td];
            float4 vb4 = *(const float4*)&sv[s][te];
            float ka[4] = {ka4.x,ka4.y,ka4.z,ka4.w};
            float vb[4] = {vb4.x,vb4.y,vb4.z,vb4.w};
            #pragma unroll
            for (int i = 0; i < 4; i++)
                #pragma unroll
                for (int j = 0; j < 4; j++)
                    acc[i][j] += ka[i]*vb[j];
        }
    }
    float* dst = g_kvpart + ((size_t)sl*256 + fh)*4096;
    #pragma unroll
    for (int i = 0; i < 4; i++)
        *(float4*)&dst[(td+i)*64 + te] = make_float4(acc[i][0],acc[i][1],acc[i][2],acc[i][3]);
    __syncthreads();
    ksr[r0][col] = kscol;
    __syncthreads();
    if (tid < 64)
        g_kspart[((size_t)sl*256+fh)*64 + tid] = ksr[0][tid]+ksr[1][tid]+ksr[2][tid]+ksr[3][tid];
}

__global__ void k_kvred(){
    int fh = blockIdx.x, tid = threadIdx.x;
    #pragma unroll
    for (int i = 0; i < 16; i++){
        int idx = tid + i*256;
        float s = 0.f;
        #pragma unroll
        for (int sl = 0; sl < 4; sl++) s += g_kvpart[((size_t)sl*256+fh)*4096 + idx];
        g_kv[(size_t)fh*4096 + idx] = s;
    }
    if (tid < 64){
        float s = 0.f;
        #pragma unroll
        for (int sl = 0; sl < 4; sl++) s += g_kspart[((size_t)sl*256+fh)*64 + tid];
        g_ksum[fh*64+tid] = s;
    }
}

__global__ void __launch_bounds__(256) k_out(const float* __restrict__ mm, float* __restrict__ out){
    int tb = blockIdx.x, h = blockIdx.y, f = blockIdx.z, tid = threadIdx.x;
    int fh = f*NH + h;
    int n0 = tb*64;
    __shared__ float sq[64][64];
    __shared__ float skv[64][64];
    __shared__ float sks[64], smw[64];
    if (tid < 64){
        sks[tid] = g_ksum[fh*64+tid];
        smw[tid] = 1.f + tanhf(mm[f*HW + n0 + tid]);
    }
    {
        float* kvf = &skv[0][0];
        const float* src = g_kv + (size_t)fh*4096;
        #pragma unroll
        for (int i = 0; i < 16; i++) kvf[tid + i*256] = src[tid + i*256];
    }
    int col = tid & 63, r0 = tid >> 6;
    const float* qb = g_qkv + (size_t)f*HW*C3 + h*DH + col;
    #pragma unroll
    for (int i = 0; i < 16; i++){
        int row = r0 + i*4;
        sq[row][col] = fmap(qb[(size_t)(n0+row)*C3]);
    }
    __syncthreads();
    int tn = (tid >> 4)*4, te = (tid & 15)*4;
    float acc[4][4] = {};
    float z[4] = {};
    #pragma unroll 8
    for (int d = 0; d < 64; d++){
        float ks = sks[d];
        float4 vb4 = *(const float4*)&skv[d][te];
        float vb[4] = {vb4.x,vb4.y,vb4.z,vb4.w};
        #pragma unroll
        for (int i = 0; i < 4; i++){
            float q = sq[tn+i][d];
            z[i] += q*ks;
            #pragma unroll
            for (int j = 0; j < 4; j++) acc[i][j] += q*vb[j];
        }
    }
    #pragma unroll
    for (int i = 0; i < 4; i++){
        float w = smw[tn+i];
        float inv = w / (w*z[i] + EPSV);
        float4 o = make_float4(acc[i][0]*inv, acc[i][1]*inv, acc[i][2]*inv, acc[i][3]*inv);
        *(float4*)(out + (size_t)(f*HW + n0 + tn + i)*CC + h*DH + te) = o;
    }
}

extern "C" void kernel_launch(void* const* d_in, const int* in_sizes, int n_in,
                              void* d_out, int out_size){
    const float* x    = (const float*)d_in[0];
    const float* mm   = (const float*)d_in[1];
    const float* W    = (const float*)d_in[2];
    const float* temb = (const float*)d_in[3];
    float* out = (float*)d_out;

    // One-time attribute set: must NOT run during graph capture (non-stream
    // runtime call inside capture can poison the captured graph).
    static int smem_set = 0;
    if (!smem_set){
        cudaFuncSetAttribute(k_gemm_mma, cudaFuncAttributeMaxDynamicSharedMemorySize, GEMM_SMEM);
        smem_set = 1;
    }

    k_prep_w<<<dim3(48,16), dim3(32,8)>>>(W);
    k_prep_x<<<36864, 256>>>(x);
    k_mean <<<dim3(32,18), 512>>>(x, mm);
    k_mw   <<<1, 32>>>();
    k_tqkv <<<dim3(32,6), 256>>>(W, temb);
    k_tattn<<<dim3(2,8), 64>>>();
    k_bias <<<dim3(32,6), 256>>>(W, temb);
    k_gemm_mma<<<dim3(12,18,32), 256, GEMM_SMEM>>>();
    k_kv   <<<dim3(4,8,32), 256>>>();
    k_kvred<<<256, 256>>>();
    k_out  <<<dim3(36,8,32), 256>>>(mm, out);
}

// round 15
// speedup vs baseline: 1.8599x; 1.0165x over previous
#include <cuda_runtime.h>
#include <cuda_bf16.h>
#include <math.h>
#include <stdint.h>

#define NF 32      // B*T frames
#define HW 2304    // 48*48 tokens per frame
#define CC 512
#define C3 1536
#define NH 8
#define DH 64
#define EPSV 1e-6f

// ---- scratch (__device__ globals; no allocations allowed) ----
static __device__ float g_xpart[NF*18*CC];
static __device__ float g_mmpart[NF*18];
static __device__ float g_qkvt[NF*C3];
static __device__ float g_tout[NF*CC];
static __device__ float g_bias[NF*C3];
static __device__ float g_qkv[113246208];                  // 32*2304*1536 f32
static __device__ __nv_bfloat16 g_xhi[NF*HW*CC];           // 75.5MB
static __device__ __nv_bfloat16 g_xlo[NF*HW*CC];
static __device__ __nv_bfloat16 g_wthi[C3*CC];             // W^T split, [1536][512]
static __device__ __nv_bfloat16 g_wtlo[C3*CC];
static __device__ float g_kvpart[4*256*4096];
static __device__ float g_kspart[4*256*64];
static __device__ float g_kv[256*4096];
static __device__ float g_ksum[256*64];

__device__ __forceinline__ float fmap(float x){ return x > 0.f ? x + 1.f : __expf(x); }

__device__ __forceinline__ uint32_t smem_to_u32(const void* p){
    uint32_t a;
    asm("{ .reg .u64 t; cvta.to.shared.u64 t, %1; cvt.u32.u64 %0, t; }" : "=r"(a) : "l"(p));
    return a;
}
__device__ __forceinline__ void cpa16(uint32_t saddr, const void* g){
    asm volatile("cp.async.cg.shared.global [%0], [%1], 16;" :: "r"(saddr), "l"(g));
}
__device__ __forceinline__ void ldsm4(uint32_t (&r)[4], uint32_t addr){
    asm volatile("ldmatrix.sync.aligned.m8n8.x4.shared.b16 {%0,%1,%2,%3}, [%4];"
        : "=r"(r[0]),"=r"(r[1]),"=r"(r[2]),"=r"(r[3]) : "r"(addr));
}
__device__ __forceinline__ void mma_bf16(float (&d)[4], const uint32_t (&a)[4], uint32_t b0, uint32_t b1){
    asm volatile("mma.sync.aligned.m16n8k16.row.col.f32.bf16.bf16.f32 "
        "{%0,%1,%2,%3},{%4,%5,%6,%7},{%8,%9},{%0,%1,%2,%3};"
        : "+f"(d[0]),"+f"(d[1]),"+f"(d[2]),"+f"(d[3])
        : "r"(a[0]),"r"(a[1]),"r"(a[2]),"r"(a[3]), "r"(b0),"r"(b1));
}

// ---- prep: split+transpose W into bf16 hi/lo [N=1536][K=512] ----
__global__ void k_prep_w(const float* __restrict__ W){
    __shared__ float t[32][33];
    int n0 = blockIdx.x*32, k0 = blockIdx.y*32;
    int tx = threadIdx.x, ty = threadIdx.y;
    #pragma unroll
    for (int i = 0; i < 32; i += 8)
        t[ty+i][tx] = W[(size_t)(k0+ty+i)*C3 + n0+tx];
    __syncthreads();
    #pragma unroll
    for (int i = 0; i < 32; i += 8){
        float v = t[tx][ty+i];
        __nv_bfloat16 hi = __float2bfloat16(v);
        __nv_bfloat16 lo = __float2bfloat16(v - __bfloat162float(hi));
        size_t idx = (size_t)(n0+ty+i)*CC + k0+tx;
        g_wthi[idx] = hi; g_wtlo[idx] = lo;
    }
}

// ---- K1 (fused): x split to bf16 hi/lo + per-frame channel sums + motion sums ----
// One pass over x instead of two (k_mean + k_prep_x fused).
__global__ void k_meanprep(const float* __restrict__ x, const float* __restrict__ mm){
    int f = blockIdx.x, s = blockIdx.y, tid = threadIdx.x;  // 512 threads
    size_t base = ((size_t)f*HW + (size_t)s*128)*CC;
    const float* xp = x + base + tid;
    __nv_bfloat16* xh = g_xhi + base + tid;
    __nv_bfloat16* xl = g_xlo + base + tid;
    float acc = 0.f;
    #pragma unroll 4
    for (int n = 0; n < 128; n++){
        float v = xp[(size_t)n*CC];
        acc += v;
        __nv_bfloat16 hi = __float2bfloat16(v);
        xh[(size_t)n*CC] = hi;
        xl[(size_t)n*CC] = __float2bfloat16(v - __bfloat162float(hi));
    }
    g_xpart[(f*18+s)*CC + tid] = acc;
    __shared__ float red[128];
    if (tid < 128) red[tid] = mm[f*HW + s*128 + tid];
    __syncthreads();
    for (int st = 64; st > 0; st >>= 1){
        if (tid < st) red[tid] += red[tid+st];
        __syncthreads();
    }
    if (tid == 0) g_mmpart[f*18+s] = red[0];
}

__global__ void k_tqkv(const float* __restrict__ W, const float* __restrict__ temb){
    int f = blockIdx.x; int cb = blockIdx.y*256; int tid = threadIdx.x;
    __shared__ float row[CC];
    for (int i = tid; i < CC; i += 256){
        float a = 0.f;
        for (int s = 0; s < 18; s++) a += g_xpart[(f*18+s)*CC + i];
        row[i] = a*(1.f/HW) + temb[i];
    }
    __syncthreads();
    int col = cb + tid;
    float acc = 0.f;
    #pragma unroll 8
    for (int k = 0; k < CC; k++) acc += row[k]*W[(size_t)k*C3 + col];
    g_qkvt[f*C3 + col] = acc;
}

// ---- temporal attention; motion weight computed inline (k_mw folded in) ----
__global__ void k_tattn(){
    int b = blockIdx.x, h = blockIdx.y, tid = threadIdx.x;
    __shared__ float sq[16][64], sk[16][64], sv[16][64], sA[16][16], smw[16];
    if (tid < 16){
        float s = 0.f;
        #pragma unroll
        for (int i = 0; i < 18; i++) s += g_mmpart[(b*16+tid)*18 + i];
        smw[tid] = 1.f + tanhf(s * (1.f/HW));
    }
    __syncthreads();
    for (int t = 0; t < 16; t++){
        int base = (b*16+t)*C3 + h*DH + tid;
        sq[t][tid] = fmap(g_qkvt[base]) * smw[t];
        sk[t][tid] = fmap(g_qkvt[base+512]);
        sv[t][tid] = g_qkvt[base+1024];
    }
    __syncthreads();
    for (int i = tid; i < 256; i += 64){
        int t = i >> 4, s2 = i & 15;
        float a = 0.f;
        #pragma unroll
        for (int d = 0; d < 64; d++) a += sq[t][d]*sk[s2][d];
        sA[t][s2] = a;
    }
    __syncthreads();
    for (int t = 0; t < 16; t++){
        float rs = 0.f, acc = 0.f;
        #pragma unroll
        for (int s2 = 0; s2 < 16; s2++){ rs += sA[t][s2]; acc += sA[t][s2]*sv[s2][tid]; }
        g_tout[(b*16+t)*CC + h*DH + tid] = acc / (rs + EPSV);
    }
}

__global__ void k_bias(const float* __restrict__ W, const float* __restrict__ temb){
    int f = blockIdx.x; int cb = blockIdx.y*256; int tid = threadIdx.x;
    __shared__ float row[CC];
    for (int i = tid; i < CC; i += 256) row[i] = temb[i] + g_tout[f*CC+i];
    __syncthreads();
    int col = cb + tid;
    float acc = 0.f;
    #pragma unroll 8
    for (int k = 0; k < CC; k++) acc += row[k]*W[(size_t)k*C3 + col];
    g_bias[f*C3 + col] = acc;
}

// ============ HMMA GEMM: qkv[f] = x[f] @ W + bias[f] (split-bf16) ============
// (byte-identical to the R10 passing version)
#define ROWP 80
#define MAT_SZ (128*ROWP)
#define STAGE_SZ (4*MAT_SZ)
#define GEMM_SMEM (2*STAGE_SZ)

__device__ __forceinline__ void load_stage(uint32_t sb,
        const __nv_bfloat16* __restrict__ aHi, const __nv_bfloat16* __restrict__ aLo,
        const __nv_bfloat16* __restrict__ bHi, const __nv_bfloat16* __restrict__ bLo,
        int k0, int tid){
    #pragma unroll
    for (int i = 0; i < 2; i++){
        int idx = tid + i*256;
        int row = idx >> 2, seg = idx & 3;
        uint32_t soff = (uint32_t)(row*ROWP + seg*16);
        size_t goff = (size_t)row*CC + k0 + seg*8;
        cpa16(sb + 0*MAT_SZ + soff, aHi + goff);
        cpa16(sb + 1*MAT_SZ + soff, aLo + goff);
        cpa16(sb + 2*MAT_SZ + soff, bHi + goff);
        cpa16(sb + 3*MAT_SZ + soff, bLo + goff);
    }
}

__global__ void __launch_bounds__(256, 2) k_gemm_mma(){
    extern __shared__ char smem[];
    uint32_t sb0 = smem_to_u32(smem);
    int tid = threadIdx.x, wid = tid >> 5, lane = tid & 31;
    int nb = blockIdx.x * 128;
    int mb = blockIdx.y * 128;
    int f  = blockIdx.z;

    const __nv_bfloat16* aHi = g_xhi + ((size_t)f*HW + mb)*CC;
    const __nv_bfloat16* aLo = g_xlo + ((size_t)f*HW + mb)*CC;
    const __nv_bfloat16* bHi = g_wthi + (size_t)nb*CC;
    const __nv_bfloat16* bLo = g_wtlo + (size_t)nb*CC;

    load_stage(sb0 + 0*STAGE_SZ, aHi, aLo, bHi, bLo, 0, tid);
    asm volatile("cp.async.commit_group;" ::: "memory");
    load_stage(sb0 + 1*STAGE_SZ, aHi, aLo, bHi, bLo, 32, tid);
    asm volatile("cp.async.commit_group;" ::: "memory");

    float acc[4][4][4] = {};
    int wm = (wid >> 2) * 64, wn = (wid & 3) * 32;
    int lrow = lane & 15, lk = lane >> 4;

    #pragma unroll 1
    for (int ks = 0; ks < 16; ks++){
        asm volatile("cp.async.wait_group 1;" ::: "memory");
        __syncthreads();
        uint32_t st = sb0 + (uint32_t)((ks & 1)*STAGE_SZ);
        #pragma unroll
        for (int s = 0; s < 2; s++){
            uint32_t bhf[2][4], blf[2][4];
            #pragma unroll
            for (int nj = 0; nj < 2; nj++){
                uint32_t addr = st + 2*MAT_SZ + (uint32_t)((wn + nj*16 + lrow)*ROWP + s*32 + lk*16);
                ldsm4(bhf[nj], addr);
                ldsm4(blf[nj], addr + MAT_SZ);
            }
            #pragma unroll
            for (int mi = 0; mi < 4; mi++){
                uint32_t ahf[4], alf[4];
                uint32_t addr = st + (uint32_t)((wm + mi*16 + lrow)*ROWP + s*32 + lk*16);
                ldsm4(ahf, addr);
                ldsm4(alf, addr + MAT_SZ);
                #pragma unroll
                for (int ni = 0; ni < 4; ni++){
                    uint32_t bh0 = bhf[ni>>1][ni&1], bh1 = bhf[ni>>1][(ni&1)+2];
                    uint32_t bl0 = blf[ni>>1][ni&1], bl1 = blf[ni>>1][(ni&1)+2];
                    mma_bf16(acc[mi][ni], ahf, bh0, bh1);
                    mma_bf16(acc[mi][ni], ahf, bl0, bl1);
                    mma_bf16(acc[mi][ni], alf, bh0, bh1);
                }
            }
        }
        __syncthreads();
        if (ks + 2 < 16)
            load_stage(st, aHi, aLo, bHi, bLo, (ks+2)*32, tid);
        asm volatile("cp.async.commit_group;" ::: "memory");
    }

    const float* bias = g_bias + f*C3 + nb;
    float* base = g_qkv + ((size_t)f*HW + mb)*C3 + nb;
    int r0 = lane >> 2, cp0 = (lane & 3) * 2;
    #pragma unroll
    for (int mi = 0; mi < 4; mi++){
        #pragma unroll
        for (int ni = 0; ni < 4; ni++){
            int col = wn + ni*8 + cp0;
            float b0 = bias[col], b1 = bias[col+1];
            float* p0 = base + (size_t)(wm + mi*16 + r0)*C3 + col;
            p0[0] = acc[mi][ni][0] + b0;
            p0[1] = acc[mi][ni][1] + b1;
            float* p1 = p0 + (size_t)8*C3;
            p1[0] = acc[mi][ni][2] + b0;
            p1[1] = acc[mi][ni][3] + b1;
        }
    }
}

// ---- K7: kv partials (R10 FFMA version — known good) ----
__global__ void __launch_bounds__(256) k_kv(){
    int sl = blockIdx.x, h = blockIdx.y, f = blockIdx.z, tid = threadIdx.x;
    int fh = f*NH + h;
    const float* base = g_qkv + (size_t)f*HW*C3;
    __shared__ float sk[64][64], sv[64][64];
    __shared__ float ksr[4][64];
    int col = tid & 63;
    int r0 = tid >> 6;
    int td = (tid >> 4) * 4;
    int te = (tid & 15) * 4;
    float acc[4][4] = {};
    float kscol = 0.f;
    for (int c = 0; c < 9; c++){
        int n0 = sl*576 + c*64;
        __syncthreads();
        #pragma unroll
        for (int i = 0; i < 16; i++){
            int row = r0 + i*4;
            const float* p = base + (size_t)(n0+row)*C3 + h*DH + col;
            float kv_ = fmap(p[512]);
            sk[row][col] = kv_;
            kscol += kv_;
            sv[row][col] = p[1024];
        }
        __syncthreads();
        #pragma unroll
        for (int s = 0; s < 64; s++){
            float4 ka4 = *(const float4*)&sk[s][td];
            float4 vb4 = *(const float4*)&sv[s][te];
            float ka[4] = {ka4.x,ka4.y,ka4.z,ka4.w};
            float vb[4] = {vb4.x,vb4.y,vb4.z,vb4.w};
            #pragma unroll
            for (int i = 0; i < 4; i++)
                #pragma unroll
                for (int j = 0; j < 4; j++)
                    acc[i][j] += ka[i]*vb[j];
        }
    }
    float* dst = g_kvpart + ((size_t)sl*256 + fh)*4096;
    #pragma unroll
    for (int i = 0; i < 4; i++)
        *(float4*)&dst[(td+i)*64 + te] = make_float4(acc[i][0],acc[i][1],acc[i][2],acc[i][3]);
    __syncthreads();
    ksr[r0][col] = kscol;
    __syncthreads();
    if (tid < 64)
        g_kspart[((size_t)sl*256+fh)*64 + tid] = ksr[0][tid]+ksr[1][tid]+ksr[2][tid]+ksr[3][tid];
}

__global__ void k_kvred(){
    int fh = blockIdx.x, tid = threadIdx.x;
    #pragma unroll
    for (int i = 0; i < 16; i++){
        int idx = tid + i*256;
        float s = 0.f;
        #pragma unroll
        for (int sl = 0; sl < 4; sl++) s += g_kvpart[((size_t)sl*256+fh)*4096 + idx];
        g_kv[(size_t)fh*4096 + idx] = s;
    }
    if (tid < 64){
        float s = 0.f;
        #pragma unroll
        for (int sl = 0; sl < 4; sl++) s += g_kspart[((size_t)sl*256+fh)*64 + tid];
        g_ksum[fh*64+tid] = s;
    }
}

// ---- K9: out (R10 FFMA version — known good) ----
__global__ void __launch_bounds__(256) k_out(const float* __restrict__ mm, float* __restrict__ out){
    int tb = blockIdx.x, h = blockIdx.y, f = blockIdx.z, tid = threadIdx.x;
    int fh = f*NH + h;
    int n0 = tb*64;
    __shared__ float sq[64][64];
    __shared__ float skv[64][64];
    __shared__ float sks[64], smw[64];
    if (tid < 64){
        sks[tid] = g_ksum[fh*64+tid];
        smw[tid] = 1.f + tanhf(mm[f*HW + n0 + tid]);
    }
    {
        float* kvf = &skv[0][0];
        const float* src = g_kv + (size_t)fh*4096;
        #pragma unroll
        for (int i = 0; i < 16; i++) kvf[tid + i*256] = src[tid + i*256];
    }
    int col = tid & 63, r0 = tid >> 6;
    const float* qb = g_qkv + (size_t)f*HW*C3 + h*DH + col;
    #pragma unroll
    for (int i = 0; i < 16; i++){
        int row = r0 + i*4;
        sq[row][col] = fmap(qb[(size_t)(n0+row)*C3]);
    }
    __syncthreads();
    int tn = (tid >> 4)*4, te = (tid & 15)*4;
    float acc[4][4] = {};
    float z[4] = {};
    #pragma unroll 8
    for (int d = 0; d < 64; d++){
        float ks = sks[d];
        float4 vb4 = *(const float4*)&skv[d][te];
        float vb[4] = {vb4.x,vb4.y,vb4.z,vb4.w};
        #pragma unroll
        for (int i = 0; i < 4; i++){
            float q = sq[tn+i][d];
            z[i] += q*ks;
            #pragma unroll
            for (int j = 0; j < 4; j++) acc[i][j] += q*vb[j];
        }
    }
    #pragma unroll
    for (int i = 0; i < 4; i++){
        float w = smw[tn+i];
        float inv = w / (w*z[i] + EPSV);
        float4 o = make_float4(acc[i][0]*inv, acc[i][1]*inv, acc[i][2]*inv, acc[i][3]*inv);
        *(float4*)(out + (size_t)(f*HW + n0 + tn + i)*CC + h*DH + te) = o;
    }
}

extern "C" void kernel_launch(void* const* d_in, const int* in_sizes, int n_in,
                              void* d_out, int out_size){
    const float* x    = (const float*)d_in[0];
    const float* mm   = (const float*)d_in[1];
    const float* W    = (const float*)d_in[2];
    const float* temb = (const float*)d_in[3];
    float* out = (float*)d_out;

    // One-time attribute set: must NOT run during graph capture.
    static int smem_set = 0;
    if (!smem_set){
        cudaFuncSetAttribute(k_gemm_mma, cudaFuncAttributeMaxDynamicSharedMemorySize, GEMM_SMEM);
        smem_set = 1;
    }

    k_prep_w  <<<dim3(48,16), dim3(32,8)>>>(W);        // 1
    k_meanprep<<<dim3(32,18), 512>>>(x, mm);           // 2
    k_tqkv    <<<dim3(32,6), 256>>>(W, temb);          // 3
    k_tattn   <<<dim3(2,8), 64>>>();                   // 4
    k_bias    <<<dim3(32,6), 256>>>(W, temb);          // 5
    k_gemm_mma<<<dim3(12,18,32), 256, GEMM_SMEM>>>();  // 6  <- ncu -s 5 -c 1 captures this
    k_kv      <<<dim3(4,8,32), 256>>>();
    k_kvred   <<<256, 256>>>();
    k_out     <<<dim3(36,8,32), 256>>>(mm, out);
}